// round 1
// baseline (speedup 1.0000x reference)
#include <cuda_runtime.h>
#include <cstdint>

#define NN 100000
#define NE 1600000
#define SCAN_NB 98   // ceil(NN/1024)

// ---------------- scratch (static __device__ arrays; no allocation) ----------
__device__ float4 g_y[NN * 64];   // [N,256] concat: [spmm(x*ns)*nd | spmm(x)]
__device__ float4 g_h[NN * 32];   // [N,128] hidden features
__device__ int    g_csr[NE];      // src ids grouped by dst
__device__ int    g_outdeg[NN];
__device__ int    g_indeg[NN];
__device__ float  g_ns[NN];
__device__ float  g_nd[NN];
__device__ int    g_rowstart[NN + 1];
__device__ int    g_cursor[NN];
__device__ int    g_blocksums[128];

// ---------------- helpers ----------------------------------------------------
__device__ __forceinline__ uint32_t f2tf(float f) {
    uint32_t u;
    asm("cvt.rna.tf32.f32 %0, %1;" : "=r"(u) : "f"(f));
    return u;
}

__device__ __forceinline__ void mma_tf32(float* c, const uint32_t* a, const uint32_t* b) {
    asm volatile(
        "mma.sync.aligned.m16n8k8.row.col.f32.tf32.tf32.f32 "
        "{%0,%1,%2,%3}, {%4,%5,%6,%7}, {%8,%9}, {%0,%1,%2,%3};\n"
        : "+f"(c[0]), "+f"(c[1]), "+f"(c[2]), "+f"(c[3])
        : "r"(a[0]), "r"(a[1]), "r"(a[2]), "r"(a[3]), "r"(b[0]), "r"(b[1]));
}

// ---------------- setup kernels ----------------------------------------------
__global__ void k_zero() {
    int i = blockIdx.x * blockDim.x + threadIdx.x;
    if (i < NN) { g_outdeg[i] = 0; g_indeg[i] = 0; }
}

__global__ void k_deg(const int* __restrict__ src, const int* __restrict__ dst) {
    int e = blockIdx.x * blockDim.x + threadIdx.x;
    if (e < NE) {
        atomicAdd(&g_outdeg[src[e]], 1);
        atomicAdd(&g_indeg[dst[e]], 1);
    }
}

__global__ void k_norm() {
    int i = blockIdx.x * blockDim.x + threadIdx.x;
    if (i < NN) {
        g_ns[i] = rsqrtf(fmaxf((float)g_outdeg[i], 1.0f));
        g_nd[i] = rsqrtf(fmaxf((float)g_indeg[i], 1.0f));
    }
}

// exclusive scan of g_indeg -> g_rowstart (3-phase)
__global__ void k_scan1() {
    __shared__ int sh[1024];
    int t = threadIdx.x;
    int i = blockIdx.x * 1024 + t;
    int v = (i < NN) ? g_indeg[i] : 0;
    sh[t] = v;
    __syncthreads();
    #pragma unroll
    for (int off = 1; off < 1024; off <<= 1) {
        int add = (t >= off) ? sh[t - off] : 0;
        __syncthreads();
        sh[t] += add;
        __syncthreads();
    }
    if (i < NN) g_rowstart[i] = sh[t] - v;  // exclusive within block
    if (t == 1023) g_blocksums[blockIdx.x] = sh[1023];
}

__global__ void k_scan2() {
    __shared__ int sh[128];
    int t = threadIdx.x;
    int v = (t < SCAN_NB) ? g_blocksums[t] : 0;
    sh[t] = v;
    __syncthreads();
    #pragma unroll
    for (int off = 1; off < 128; off <<= 1) {
        int add = (t >= off) ? sh[t - off] : 0;
        __syncthreads();
        sh[t] += add;
        __syncthreads();
    }
    if (t < SCAN_NB) g_blocksums[t] = sh[t] - v;  // exclusive block offsets
}

__global__ void k_scan3() {
    int i = blockIdx.x * blockDim.x + threadIdx.x;
    if (i < NN) {
        int rs = g_rowstart[i] + g_blocksums[i >> 10];
        g_rowstart[i] = rs;
        g_cursor[i] = rs;
    }
    if (i == 0) g_rowstart[NN] = NE;
}

__global__ void k_csr(const int* __restrict__ src, const int* __restrict__ dst) {
    int e = blockIdx.x * blockDim.x + threadIdx.x;
    if (e < NE) {
        int pos = atomicAdd(&g_cursor[dst[e]], 1);
        g_csr[pos] = src[e];
    }
}

// ---------------- SpMM: warp per node, dual accumulation ----------------------
// y[i] = [ (sum_j x[j]*ns[j]) * nd[i]  |  sum_j x[j] ]   for j in in-neighbors
__global__ __launch_bounds__(256) void k_spmm(const float4* __restrict__ x) {
    int w    = (blockIdx.x * 256 + threadIdx.x) >> 5;
    int lane = threadIdx.x & 31;
    if (w >= NN) return;
    int s = g_rowstart[w];
    int e = g_rowstart[w + 1];
    float4 a1 = make_float4(0.f, 0.f, 0.f, 0.f);
    float4 a2 = make_float4(0.f, 0.f, 0.f, 0.f);
    int p = s;
    for (; p + 1 < e; p += 2) {
        int j0 = g_csr[p];
        int j1 = g_csr[p + 1];
        float n0 = g_ns[j0];
        float n1 = g_ns[j1];
        float4 v0 = x[(size_t)j0 * 32 + lane];
        float4 v1 = x[(size_t)j1 * 32 + lane];
        a2.x += v0.x + v1.x; a2.y += v0.y + v1.y;
        a2.z += v0.z + v1.z; a2.w += v0.w + v1.w;
        a1.x = fmaf(v0.x, n0, fmaf(v1.x, n1, a1.x));
        a1.y = fmaf(v0.y, n0, fmaf(v1.y, n1, a1.y));
        a1.z = fmaf(v0.z, n0, fmaf(v1.z, n1, a1.z));
        a1.w = fmaf(v0.w, n0, fmaf(v1.w, n1, a1.w));
    }
    if (p < e) {
        int j0 = g_csr[p];
        float n0 = g_ns[j0];
        float4 v0 = x[(size_t)j0 * 32 + lane];
        a2.x += v0.x; a2.y += v0.y; a2.z += v0.z; a2.w += v0.w;
        a1.x = fmaf(v0.x, n0, a1.x);
        a1.y = fmaf(v0.y, n0, a1.y);
        a1.z = fmaf(v0.z, n0, a1.z);
        a1.w = fmaf(v0.w, n0, a1.w);
    }
    float nd = g_nd[w];
    float4 o1 = make_float4(a1.x * nd, a1.y * nd, a1.z * nd, a1.w * nd);
    g_y[(size_t)w * 64 + lane]      = o1;
    g_y[(size_t)w * 64 + 32 + lane] = a2;
}

// ---------------- GEMM: C[M,BN] = A[M,256] @ [W0;W1] + bias (tf32 mma) --------
template <int BN, bool RELU>
__global__ __launch_bounds__(256) void k_gemm(
    const float* __restrict__ A, const float* __restrict__ W0,
    const float* __restrict__ W1, const float* __restrict__ bias,
    float* __restrict__ C, int M)
{
    constexpr int BM = 128, BK = 32, K = 256;
    constexpr int AS = 36;        // padded A stride (conflict-free frag reads)
    constexpr int BS = BN + 8;    // padded B stride
    constexpr int NT = BN / 16;   // n-tiles per warp (warp tile 32 x BN/2)
    __shared__ uint32_t sA[BM * AS];
    __shared__ uint32_t sB[BK * BS];

    const int tid  = threadIdx.x;
    const int warp = tid >> 5, lane = tid & 31;
    const int grp  = lane >> 2, tig = lane & 3;
    const int wm   = (warp >> 1) * 32;
    const int wn   = (warp & 1) * (BN / 2);
    const int blockRow = blockIdx.x * BM;

    float acc[2][NT][4];
    #pragma unroll
    for (int mt = 0; mt < 2; mt++)
        #pragma unroll
        for (int nt = 0; nt < NT; nt++)
            #pragma unroll
            for (int r = 0; r < 4; r++) acc[mt][nt][r] = 0.f;

    for (int kc = 0; kc < K / BK; ++kc) {
        // stage A tile (128x32) as tf32
        #pragma unroll
        for (int it = 0; it < 4; ++it) {
            int idx = tid + it * 256;          // 0..1023 float4 slots
            int r = idx >> 3, c = (idx & 7) * 4;
            int grow = blockRow + r;
            float4 v = make_float4(0.f, 0.f, 0.f, 0.f);
            if (grow < M)
                v = *reinterpret_cast<const float4*>(&A[(size_t)grow * K + kc * BK + c]);
            uint4 u;
            u.x = f2tf(v.x); u.y = f2tf(v.y); u.z = f2tf(v.z); u.w = f2tf(v.w);
            *reinterpret_cast<uint4*>(&sA[r * AS + c]) = u;
        }
        // stage B tile (32xBN), rows k<128 from W0, else W1
        #pragma unroll
        for (int it = 0; it < (BK * BN / 4) / 256; ++it) {
            int idx = tid + it * 256;
            int r = idx / (BN / 4), c = (idx % (BN / 4)) * 4;
            int gk = kc * BK + r;
            const float* Wp = (gk < 128) ? (W0 + (size_t)gk * BN + c)
                                         : (W1 + (size_t)(gk - 128) * BN + c);
            float4 v = *reinterpret_cast<const float4*>(Wp);
            uint4 u;
            u.x = f2tf(v.x); u.y = f2tf(v.y); u.z = f2tf(v.z); u.w = f2tf(v.w);
            *reinterpret_cast<uint4*>(&sB[r * BS + c]) = u;
        }
        __syncthreads();

        #pragma unroll
        for (int ks = 0; ks < 4; ++ks) {
            uint32_t af[2][4];
            #pragma unroll
            for (int mt = 0; mt < 2; mt++) {
                int row = wm + mt * 16 + grp;
                af[mt][0] = sA[row * AS + ks * 8 + tig];
                af[mt][1] = sA[(row + 8) * AS + ks * 8 + tig];
                af[mt][2] = sA[row * AS + ks * 8 + tig + 4];
                af[mt][3] = sA[(row + 8) * AS + ks * 8 + tig + 4];
            }
            uint32_t bf[NT][2];
            #pragma unroll
            for (int nt = 0; nt < NT; nt++) {
                int col = wn + nt * 8 + grp;
                bf[nt][0] = sB[(ks * 8 + tig) * BS + col];
                bf[nt][1] = sB[(ks * 8 + tig + 4) * BS + col];
            }
            #pragma unroll
            for (int mt = 0; mt < 2; mt++)
                #pragma unroll
                for (int nt = 0; nt < NT; nt++)
                    mma_tf32(acc[mt][nt], af[mt], bf[nt]);
        }
        __syncthreads();
    }

    // epilogue: bias (+relu), float2 stores
    #pragma unroll
    for (int mt = 0; mt < 2; ++mt) {
        int r0 = blockRow + wm + mt * 16 + grp;
        int r1 = r0 + 8;
        #pragma unroll
        for (int nt = 0; nt < NT; ++nt) {
            int col = wn + nt * 8 + 2 * tig;
            float b0v = bias[col], b1v = bias[col + 1];
            float v0 = acc[mt][nt][0] + b0v;
            float v1 = acc[mt][nt][1] + b1v;
            float v2 = acc[mt][nt][2] + b0v;
            float v3 = acc[mt][nt][3] + b1v;
            if (RELU) {
                v0 = fmaxf(v0, 0.f); v1 = fmaxf(v1, 0.f);
                v2 = fmaxf(v2, 0.f); v3 = fmaxf(v3, 0.f);
            }
            if (r0 < M)
                *reinterpret_cast<float2*>(&C[(size_t)r0 * BN + col]) = make_float2(v0, v1);
            if (r1 < M)
                *reinterpret_cast<float2*>(&C[(size_t)r1 * BN + col]) = make_float2(v2, v3);
        }
    }
}

// ---------------- launcher ----------------------------------------------------
extern "C" void kernel_launch(void* const* d_in, const int* in_sizes, int n_in,
                              void* d_out, int out_size) {
    const float* raw_x = (const float*)d_in[0];
    const int*   src   = (const int*)d_in[1];
    const int*   dst   = (const int*)d_in[2];
    const float* w0    = (const float*)d_in[3];
    const float* b0    = (const float*)d_in[4];
    const float* w1    = (const float*)d_in[5];
    const float* b1    = (const float*)d_in[6];
    const float* w2    = (const float*)d_in[7];
    const float* b2    = (const float*)d_in[8];
    const float* rw0   = (const float*)d_in[9];
    const float* rw1   = (const float*)d_in[10];
    const float* rw2   = (const float*)d_in[11];
    float* out = (float*)d_out;

    void *py = nullptr, *ph = nullptr;
    cudaGetSymbolAddress(&py, g_y);
    cudaGetSymbolAddress(&ph, g_h);

    const int TB = 256;
    // graph preprocessing (once per call, reused by all 3 layers)
    k_zero<<<(NN + TB - 1) / TB, TB>>>();
    k_deg<<<(NE + TB - 1) / TB, TB>>>(src, dst);
    k_norm<<<(NN + TB - 1) / TB, TB>>>();
    k_scan1<<<SCAN_NB, 1024>>>();
    k_scan2<<<1, 128>>>();
    k_scan3<<<(NN + TB - 1) / TB, TB>>>();
    k_csr<<<(NE + TB - 1) / TB, TB>>>(src, dst);

    const int SPMM_BLOCKS = (NN * 32 + TB - 1) / TB;  // one warp per node
    const int GEMM_BLOCKS = (NN + 127) / 128;

    // layer 1
    k_spmm<<<SPMM_BLOCKS, TB>>>((const float4*)raw_x);
    k_gemm<128, true><<<GEMM_BLOCKS, TB>>>((const float*)py, w0, rw0, b0, (float*)ph, NN);
    // layer 2
    k_spmm<<<SPMM_BLOCKS, TB>>>((const float4*)ph);
    k_gemm<128, true><<<GEMM_BLOCKS, TB>>>((const float*)py, w1, rw1, b1, (float*)ph, NN);
    // layer 3 (no relu, F=64) -> d_out
    k_spmm<<<SPMM_BLOCKS, TB>>>((const float4*)ph);
    k_gemm<64, false><<<GEMM_BLOCKS, TB>>>((const float*)py, w2, rw2, b2, out, NN);
}

// round 2
// speedup vs baseline: 1.1372x; 1.1372x over previous
#include <cuda_runtime.h>
#include <cstdint>

#define NN 100000
#define NN_PAD 100096          // 782 * 128, pads GEMM A reads
#define NE 1600000
#define SCAN_NB 98             // ceil(NN/1024)

// ---------------- scratch (static __device__ arrays; no allocation) ----------
__device__ uint4  g_y[NN_PAD * 64];   // [N,256] tf32 bits: [spmm(x*ns)*nd | spmm(x)]
__device__ float4 g_h[NN * 32];       // [N,128] hidden features (fp32)
__device__ int    g_csr[NE];          // src ids grouped by dst
__device__ int    g_outdeg[NN];
__device__ int    g_indeg[NN];
__device__ float  g_ns[NN];
__device__ float  g_nd[NN];
__device__ int    g_rowstart[NN + 1];
__device__ int    g_cursor[NN];
__device__ int    g_blocksums[128];
__device__ uint4  g_wt0[256 * 128 / 4];   // [256,128] tf32 bits: [w0 ; rw0]
__device__ uint4  g_wt1[256 * 128 / 4];   // [256,128] tf32 bits: [w1 ; rw1]
__device__ uint4  g_wt2[256 * 64 / 4];    // [256,64]  tf32 bits: [w2 ; rw2]

// ---------------- helpers ----------------------------------------------------
__device__ __forceinline__ uint32_t f2tf(float f) {
    uint32_t u;
    asm("cvt.rna.tf32.f32 %0, %1;" : "=r"(u) : "f"(f));
    return u;
}

__device__ __forceinline__ void mma_tf32(float* c, const uint32_t* a, const uint32_t* b) {
    asm volatile(
        "mma.sync.aligned.m16n8k8.row.col.f32.tf32.tf32.f32 "
        "{%0,%1,%2,%3}, {%4,%5,%6,%7}, {%8,%9}, {%0,%1,%2,%3};\n"
        : "+f"(c[0]), "+f"(c[1]), "+f"(c[2]), "+f"(c[3])
        : "r"(a[0]), "r"(a[1]), "r"(a[2]), "r"(a[3]), "r"(b[0]), "r"(b[1]));
}

__device__ __forceinline__ void cp16(uint32_t dst, const void* src) {
    asm volatile("cp.async.cg.shared.global [%0], [%1], 16;\n" :: "r"(dst), "l"(src));
}
__device__ __forceinline__ void cpcommit() {
    asm volatile("cp.async.commit_group;\n");
}
template <int N>
__device__ __forceinline__ void cpwait() {
    asm volatile("cp.async.wait_group %0;\n" :: "n"(N));
}

// ---------------- setup kernels ----------------------------------------------
__global__ void k_deg(const int4* __restrict__ src4, const int4* __restrict__ dst4) {
    int e = blockIdx.x * blockDim.x + threadIdx.x;
    if (e < NE / 4) {
        int4 s = src4[e];
        int4 d = dst4[e];
        atomicAdd(&g_outdeg[s.x], 1); atomicAdd(&g_outdeg[s.y], 1);
        atomicAdd(&g_outdeg[s.z], 1); atomicAdd(&g_outdeg[s.w], 1);
        atomicAdd(&g_indeg[d.x], 1);  atomicAdd(&g_indeg[d.y], 1);
        atomicAdd(&g_indeg[d.z], 1);  atomicAdd(&g_indeg[d.w], 1);
    }
}

// exclusive scan of g_indeg: per-block scan + blocksums
__global__ void k_scan1() {
    __shared__ int sh[1024];
    int t = threadIdx.x;
    int i = blockIdx.x * 1024 + t;
    int v = (i < NN) ? g_indeg[i] : 0;
    sh[t] = v;
    __syncthreads();
    #pragma unroll
    for (int off = 1; off < 1024; off <<= 1) {
        int add = (t >= off) ? sh[t - off] : 0;
        __syncthreads();
        sh[t] += add;
        __syncthreads();
    }
    if (i < NN) g_rowstart[i] = sh[t] - v;  // exclusive within block
    if (t == 1023) g_blocksums[blockIdx.x] = sh[1023];
}

// apply block offsets + init cursor + compute norms (fused scan2+scan3+norm)
__global__ void k_scan23() {
    __shared__ int bs[SCAN_NB];
    __shared__ int pre[SCAN_NB];
    int t = threadIdx.x;
    if (t < SCAN_NB) bs[t] = g_blocksums[t];
    __syncthreads();
    if (t == 0) {
        int run = 0;
        #pragma unroll 1
        for (int i = 0; i < SCAN_NB; ++i) { pre[i] = run; run += bs[i]; }
    }
    __syncthreads();
    int i = blockIdx.x * blockDim.x + t;
    if (i < NN) {
        int rs = g_rowstart[i] + pre[i >> 10];
        g_rowstart[i] = rs;
        g_cursor[i] = rs;
        g_ns[i] = rsqrtf(fmaxf((float)g_outdeg[i], 1.0f));
        g_nd[i] = rsqrtf(fmaxf((float)g_indeg[i], 1.0f));
    }
    if (i == 0) g_rowstart[NN] = NE;
}

__global__ void k_csr(const int4* __restrict__ src4, const int4* __restrict__ dst4) {
    int e = blockIdx.x * blockDim.x + threadIdx.x;
    if (e < NE / 4) {
        int4 s = src4[e];
        int4 d = dst4[e];
        int p0 = atomicAdd(&g_cursor[d.x], 1); g_csr[p0] = s.x;
        int p1 = atomicAdd(&g_cursor[d.y], 1); g_csr[p1] = s.y;
        int p2 = atomicAdd(&g_cursor[d.z], 1); g_csr[p2] = s.z;
        int p3 = atomicAdd(&g_cursor[d.w], 1); g_csr[p3] = s.w;
    }
}

// pre-convert concatenated weights to tf32 bits
__global__ void k_wprep(const float* __restrict__ w0, const float* __restrict__ rw0,
                        const float* __restrict__ w1, const float* __restrict__ rw1,
                        const float* __restrict__ w2, const float* __restrict__ rw2) {
    int i = blockIdx.x * blockDim.x + threadIdx.x;  // 0..81919
    if (i < 32768) {
        int r = i >> 7, c = i & 127;
        float v = (r < 128) ? w0[r * 128 + c] : rw0[(r - 128) * 128 + c];
        ((uint32_t*)g_wt0)[i] = f2tf(v);
    } else if (i < 65536) {
        int j = i - 32768;
        int r = j >> 7, c = j & 127;
        float v = (r < 128) ? w1[r * 128 + c] : rw1[(r - 128) * 128 + c];
        ((uint32_t*)g_wt1)[j] = f2tf(v);
    } else if (i < 81920) {
        int j = i - 65536;
        int r = j >> 6, c = j & 63;
        float v = (r < 128) ? w2[r * 64 + c] : rw2[(r - 128) * 64 + c];
        ((uint32_t*)g_wt2)[j] = f2tf(v);
    }
}

// ---------------- SpMM: warp per node, dual accumulation, unroll 4 ------------
// y[i] = tf32[ (sum_j x[j]*ns[j]) * nd[i]  |  sum_j x[j] ]  for j in in-nbrs(i)
__global__ __launch_bounds__(256) void k_spmm(const float4* __restrict__ x) {
    int w    = (blockIdx.x * 256 + threadIdx.x) >> 5;
    int lane = threadIdx.x & 31;
    if (w >= NN) return;
    int s = g_rowstart[w];
    int e = g_rowstart[w + 1];
    float4 a1 = make_float4(0.f, 0.f, 0.f, 0.f);
    float4 a2 = make_float4(0.f, 0.f, 0.f, 0.f);
    int p = s;
    for (; p + 3 < e; p += 4) {
        int j0 = g_csr[p],     j1 = g_csr[p + 1];
        int j2 = g_csr[p + 2], j3 = g_csr[p + 3];
        float n0 = g_ns[j0], n1 = g_ns[j1], n2 = g_ns[j2], n3 = g_ns[j3];
        float4 v0 = x[(size_t)j0 * 32 + lane];
        float4 v1 = x[(size_t)j1 * 32 + lane];
        float4 v2 = x[(size_t)j2 * 32 + lane];
        float4 v3 = x[(size_t)j3 * 32 + lane];
        a2.x += (v0.x + v1.x) + (v2.x + v3.x);
        a2.y += (v0.y + v1.y) + (v2.y + v3.y);
        a2.z += (v0.z + v1.z) + (v2.z + v3.z);
        a2.w += (v0.w + v1.w) + (v2.w + v3.w);
        a1.x = fmaf(v0.x, n0, fmaf(v1.x, n1, fmaf(v2.x, n2, fmaf(v3.x, n3, a1.x))));
        a1.y = fmaf(v0.y, n0, fmaf(v1.y, n1, fmaf(v2.y, n2, fmaf(v3.y, n3, a1.y))));
        a1.z = fmaf(v0.z, n0, fmaf(v1.z, n1, fmaf(v2.z, n2, fmaf(v3.z, n3, a1.z))));
        a1.w = fmaf(v0.w, n0, fmaf(v1.w, n1, fmaf(v2.w, n2, fmaf(v3.w, n3, a1.w))));
    }
    for (; p < e; ++p) {
        int j0 = g_csr[p];
        float n0 = g_ns[j0];
        float4 v0 = x[(size_t)j0 * 32 + lane];
        a2.x += v0.x; a2.y += v0.y; a2.z += v0.z; a2.w += v0.w;
        a1.x = fmaf(v0.x, n0, a1.x);
        a1.y = fmaf(v0.y, n0, a1.y);
        a1.z = fmaf(v0.z, n0, a1.z);
        a1.w = fmaf(v0.w, n0, a1.w);
    }
    float nd = g_nd[w];
    uint4 o1, o2;
    o1.x = f2tf(a1.x * nd); o1.y = f2tf(a1.y * nd);
    o1.z = f2tf(a1.z * nd); o1.w = f2tf(a1.w * nd);
    o2.x = f2tf(a2.x); o2.y = f2tf(a2.y); o2.z = f2tf(a2.z); o2.w = f2tf(a2.w);
    g_y[(size_t)w * 64 + lane]      = o1;
    g_y[(size_t)w * 64 + 32 + lane] = o2;
}

// ---------------- GEMM: C[M,BN] = A[M,256] @ B[256,BN] + bias ----------------
// A, B are pre-converted tf32 bit patterns. cp.async double-buffered pipeline.
template <int BN, bool RELU>
__global__ __launch_bounds__(256) void k_gemm(
    const uint32_t* __restrict__ A, const uint32_t* __restrict__ Bw,
    const float* __restrict__ bias, float* __restrict__ C, int M)
{
    constexpr int BM = 128, BK = 32, K = 256;
    constexpr int AS = 36;         // padded A stride (conflict-free frag reads)
    constexpr int BS = BN + 8;     // padded B stride
    constexpr int NT = BN / 16;    // n-tiles per warp (warp tile 32 x BN/2)
    constexpr int ABUF = BM * AS;  // u32 per A stage
    constexpr int BBUF = BK * BS;  // u32 per B stage

    extern __shared__ uint32_t dynsmem[];
    uint32_t* sA = dynsmem;              // 2 * ABUF
    uint32_t* sB = dynsmem + 2 * ABUF;   // 2 * BBUF
    const uint32_t saddrA = (uint32_t)__cvta_generic_to_shared(sA);
    const uint32_t saddrB = (uint32_t)__cvta_generic_to_shared(sB);

    const int tid  = threadIdx.x;
    const int warp = tid >> 5, lane = tid & 31;
    const int grp  = lane >> 2, tig = lane & 3;
    const int wm   = (warp >> 1) * 32;
    const int wn   = (warp & 1) * (BN / 2);
    const int blockRow = blockIdx.x * BM;

    auto stage = [&](int kc, int buf) {
        #pragma unroll
        for (int it = 0; it < 4; ++it) {      // A tile: 128x32
            int idx = tid + it * 256;
            int r = idx >> 3, c = (idx & 7) * 4;
            cp16(saddrA + (uint32_t)(buf * ABUF + r * AS + c) * 4,
                 A + (size_t)(blockRow + r) * K + kc * BK + c);
        }
        #pragma unroll
        for (int it = 0; it < (BK * BN / 4) / 256; ++it) {  // B tile: 32xBN
            int idx = tid + it * 256;
            int r = idx / (BN / 4), c = (idx % (BN / 4)) * 4;
            cp16(saddrB + (uint32_t)(buf * BBUF + r * BS + c) * 4,
                 Bw + (size_t)(kc * BK + r) * BN + c);
        }
        cpcommit();
    };

    float acc[2][NT][4];
    #pragma unroll
    for (int mt = 0; mt < 2; mt++)
        #pragma unroll
        for (int nt = 0; nt < NT; nt++)
            #pragma unroll
            for (int r = 0; r < 4; r++) acc[mt][nt][r] = 0.f;

    stage(0, 0);
    #pragma unroll
    for (int kc = 0; kc < K / BK; ++kc) {
        int buf = kc & 1;
        if (kc + 1 < K / BK) {
            stage(kc + 1, buf ^ 1);
            cpwait<1>();
        } else {
            cpwait<0>();
        }
        __syncthreads();

        const uint32_t* cA = sA + buf * ABUF;
        const uint32_t* cB = sB + buf * BBUF;
        #pragma unroll
        for (int ks = 0; ks < 4; ++ks) {
            uint32_t af[2][4];
            #pragma unroll
            for (int mt = 0; mt < 2; mt++) {
                int row = wm + mt * 16 + grp;
                af[mt][0] = cA[row * AS + ks * 8 + tig];
                af[mt][1] = cA[(row + 8) * AS + ks * 8 + tig];
                af[mt][2] = cA[row * AS + ks * 8 + tig + 4];
                af[mt][3] = cA[(row + 8) * AS + ks * 8 + tig + 4];
            }
            uint32_t bf[NT][2];
            #pragma unroll
            for (int nt = 0; nt < NT; nt++) {
                int col = wn + nt * 8 + grp;
                bf[nt][0] = cB[(ks * 8 + tig) * BS + col];
                bf[nt][1] = cB[(ks * 8 + tig + 4) * BS + col];
            }
            #pragma unroll
            for (int mt = 0; mt < 2; mt++)
                #pragma unroll
                for (int nt = 0; nt < NT; nt++)
                    mma_tf32(acc[mt][nt], af[mt], bf[nt]);
        }
        __syncthreads();
    }

    // epilogue: bias (+relu), float2 stores
    #pragma unroll
    for (int mt = 0; mt < 2; ++mt) {
        int r0 = blockRow + wm + mt * 16 + grp;
        int r1 = r0 + 8;
        #pragma unroll
        for (int nt = 0; nt < NT; ++nt) {
            int col = wn + nt * 8 + 2 * tig;
            float b0v = bias[col], b1v = bias[col + 1];
            float v0 = acc[mt][nt][0] + b0v;
            float v1 = acc[mt][nt][1] + b1v;
            float v2 = acc[mt][nt][2] + b0v;
            float v3 = acc[mt][nt][3] + b1v;
            if (RELU) {
                v0 = fmaxf(v0, 0.f); v1 = fmaxf(v1, 0.f);
                v2 = fmaxf(v2, 0.f); v3 = fmaxf(v3, 0.f);
            }
            if (r0 < M)
                *reinterpret_cast<float2*>(&C[(size_t)r0 * BN + col]) = make_float2(v0, v1);
            if (r1 < M)
                *reinterpret_cast<float2*>(&C[(size_t)r1 * BN + col]) = make_float2(v2, v3);
        }
    }
}

// ---------------- launcher ----------------------------------------------------
extern "C" void kernel_launch(void* const* d_in, const int* in_sizes, int n_in,
                              void* d_out, int out_size) {
    const float* raw_x = (const float*)d_in[0];
    const int*   src   = (const int*)d_in[1];
    const int*   dst   = (const int*)d_in[2];
    const float* w0    = (const float*)d_in[3];
    const float* b0    = (const float*)d_in[4];
    const float* w1    = (const float*)d_in[5];
    const float* b1    = (const float*)d_in[6];
    const float* w2    = (const float*)d_in[7];
    const float* b2    = (const float*)d_in[8];
    const float* rw0   = (const float*)d_in[9];
    const float* rw1   = (const float*)d_in[10];
    const float* rw2   = (const float*)d_in[11];
    float* out = (float*)d_out;

    void *py = nullptr, *ph = nullptr, *pod = nullptr, *pid = nullptr;
    void *pw0 = nullptr, *pw1 = nullptr, *pw2 = nullptr;
    cudaGetSymbolAddress(&py, g_y);
    cudaGetSymbolAddress(&ph, g_h);
    cudaGetSymbolAddress(&pod, g_outdeg);
    cudaGetSymbolAddress(&pid, g_indeg);
    cudaGetSymbolAddress(&pw0, g_wt0);
    cudaGetSymbolAddress(&pw1, g_wt1);
    cudaGetSymbolAddress(&pw2, g_wt2);

    constexpr int SMEM128 = (2 * 128 * 36 + 2 * 32 * 136) * 4;  // 71680
    constexpr int SMEM64  = (2 * 128 * 36 + 2 * 32 * 72) * 4;   // 55296
    cudaFuncSetAttribute(k_gemm<128, true>,
                         cudaFuncAttributeMaxDynamicSharedMemorySize, SMEM128);
    cudaFuncSetAttribute(k_gemm<64, false>,
                         cudaFuncAttributeMaxDynamicSharedMemorySize, SMEM64);

    const int TB = 256;
    // graph preprocessing (once per call, reused by all 3 layers)
    cudaMemsetAsync(pod, 0, NN * sizeof(int));
    cudaMemsetAsync(pid, 0, NN * sizeof(int));
    k_deg<<<(NE / 4 + TB - 1) / TB, TB>>>((const int4*)src, (const int4*)dst);
    k_scan1<<<SCAN_NB, 1024>>>();
    k_scan23<<<(NN + TB - 1) / TB, TB>>>();
    k_csr<<<(NE / 4 + TB - 1) / TB, TB>>>((const int4*)src, (const int4*)dst);

    const int SPMM_BLOCKS = (NN * 32 + TB - 1) / TB;  // one warp per node
    const int GEMM_BLOCKS = NN_PAD / 128;             // 782

    // layer 1
    k_spmm<<<SPMM_BLOCKS, TB>>>((const float4*)raw_x);
    k_wprep<<<(81920 + TB - 1) / TB, TB>>>(w0, rw0, w1, rw1, w2, rw2);
    k_gemm<128, true><<<GEMM_BLOCKS, TB, SMEM128>>>(
        (const uint32_t*)py, (const uint32_t*)pw0, b0, (float*)ph, NN);
    // layer 2
    k_spmm<<<SPMM_BLOCKS, TB>>>((const float4*)ph);
    k_gemm<128, true><<<GEMM_BLOCKS, TB, SMEM128>>>(
        (const uint32_t*)py, (const uint32_t*)pw1, b1, (float*)ph, NN);
    // layer 3 (no relu, F=64) -> d_out
    k_spmm<<<SPMM_BLOCKS, TB>>>((const float4*)ph);
    k_gemm<64, false><<<GEMM_BLOCKS, TB, SMEM64>>>(
        (const uint32_t*)py, (const uint32_t*)pw2, b2, out, NN);
}

// round 3
// speedup vs baseline: 1.2093x; 1.0634x over previous
#include <cuda_runtime.h>
#include <cuda_fp16.h>
#include <cstdint>

#define NN 100000
#define NN_PAD 100096          // 782 * 128, pads GEMM A reads
#define NE 1600000
#define SCAN_NB 98             // ceil(NN/1024)

// ---------------- scratch (static __device__ arrays; no allocation) ----------
__device__ uint4  g_y[NN_PAD * 64];   // [N,256] tf32 bits: [spmm(x*ns)*nd | spmm(x)]
__device__ uint2  g_xh[NN * 32];      // [N,128] fp16 features (x, then hidden h)
__device__ int    g_csr[NE];          // src ids grouped by dst
__device__ int    g_rank[NE];         // per-edge rank within its dst bucket
__device__ int    g_outdeg[NN];
__device__ int    g_indeg[NN];
__device__ float  g_ns[NN];
__device__ float  g_nd[NN];
__device__ int    g_rowstart[NN + 1];
__device__ int    g_blocksums[128];
__device__ uint4  g_wt0[256 * 128 / 4];   // [256,128] tf32 bits: [w0 ; rw0]
__device__ uint4  g_wt1[256 * 128 / 4];   // [256,128] tf32 bits: [w1 ; rw1]
__device__ uint4  g_wt2[256 * 64 / 4];    // [256,64]  tf32 bits: [w2 ; rw2]

// ---------------- helpers ----------------------------------------------------
__device__ __forceinline__ uint32_t f2tf(float f) {
    uint32_t u;
    asm("cvt.rna.tf32.f32 %0, %1;" : "=r"(u) : "f"(f));
    return u;
}

__device__ __forceinline__ void mma_tf32(float* c, const uint32_t* a, const uint32_t* b) {
    asm volatile(
        "mma.sync.aligned.m16n8k8.row.col.f32.tf32.tf32.f32 "
        "{%0,%1,%2,%3}, {%4,%5,%6,%7}, {%8,%9}, {%0,%1,%2,%3};\n"
        : "+f"(c[0]), "+f"(c[1]), "+f"(c[2]), "+f"(c[3])
        : "r"(a[0]), "r"(a[1]), "r"(a[2]), "r"(a[3]), "r"(b[0]), "r"(b[1]));
}

__device__ __forceinline__ void cp16(uint32_t dst, const void* src) {
    asm volatile("cp.async.cg.shared.global [%0], [%1], 16;\n" :: "r"(dst), "l"(src));
}
__device__ __forceinline__ void cpcommit() {
    asm volatile("cp.async.commit_group;\n");
}
template <int N>
__device__ __forceinline__ void cpwait() {
    asm volatile("cp.async.wait_group %0;\n" :: "n"(N));
}

// ---------------- fused prep: weights->tf32, zero degs, raw_x->fp16 ----------
// work ranges: [0,81920) weights | [81920,106920) zero outdeg | [106920,131920)
// zero indeg | [131920, 3331920) x conversion (float4 -> 4x half)
__global__ void k_prep(const float4* __restrict__ raw_x,
                       const float* __restrict__ w0, const float* __restrict__ rw0,
                       const float* __restrict__ w1, const float* __restrict__ rw1,
                       const float* __restrict__ w2, const float* __restrict__ rw2) {
    int i = blockIdx.x * blockDim.x + threadIdx.x;
    if (i < 32768) {
        int r = i >> 7, c = i & 127;
        float v = (r < 128) ? w0[r * 128 + c] : rw0[(r - 128) * 128 + c];
        ((uint32_t*)g_wt0)[i] = f2tf(v);
    } else if (i < 65536) {
        int j = i - 32768;
        int r = j >> 7, c = j & 127;
        float v = (r < 128) ? w1[r * 128 + c] : rw1[(r - 128) * 128 + c];
        ((uint32_t*)g_wt1)[j] = f2tf(v);
    } else if (i < 81920) {
        int j = i - 65536;
        int r = j >> 6, c = j & 63;
        float v = (r < 128) ? w2[r * 64 + c] : rw2[(r - 128) * 64 + c];
        ((uint32_t*)g_wt2)[j] = f2tf(v);
    } else if (i < 106920) {
        ((int4*)g_outdeg)[i - 81920] = make_int4(0, 0, 0, 0);
    } else if (i < 131920) {
        ((int4*)g_indeg)[i - 106920] = make_int4(0, 0, 0, 0);
    } else if (i < 3331920) {
        int j = i - 131920;                 // float4 index == uint2 index
        float4 v = raw_x[j];
        __half2 h0 = __floats2half2_rn(v.x, v.y);
        __half2 h1 = __floats2half2_rn(v.z, v.w);
        uint2 u;
        u.x = *reinterpret_cast<uint32_t*>(&h0);
        u.y = *reinterpret_cast<uint32_t*>(&h1);
        g_xh[j] = u;
    }
}

// ---------------- degree count + per-edge dst rank ----------------------------
__global__ void k_deg(const int4* __restrict__ src4, const int4* __restrict__ dst4) {
    int e = blockIdx.x * blockDim.x + threadIdx.x;
    if (e < NE / 4) {
        int4 s = src4[e];
        int4 d = dst4[e];
        atomicAdd(&g_outdeg[s.x], 1); atomicAdd(&g_outdeg[s.y], 1);
        atomicAdd(&g_outdeg[s.z], 1); atomicAdd(&g_outdeg[s.w], 1);
        int4 r;
        r.x = atomicAdd(&g_indeg[d.x], 1);
        r.y = atomicAdd(&g_indeg[d.y], 1);
        r.z = atomicAdd(&g_indeg[d.z], 1);
        r.w = atomicAdd(&g_indeg[d.w], 1);
        ((int4*)g_rank)[e] = r;
    }
}

// exclusive scan of g_indeg: per-block scan + blocksums
__global__ void k_scan1() {
    __shared__ int sh[1024];
    int t = threadIdx.x;
    int i = blockIdx.x * 1024 + t;
    int v = (i < NN) ? g_indeg[i] : 0;
    sh[t] = v;
    __syncthreads();
    #pragma unroll
    for (int off = 1; off < 1024; off <<= 1) {
        int add = (t >= off) ? sh[t - off] : 0;
        __syncthreads();
        sh[t] += add;
        __syncthreads();
    }
    if (i < NN) g_rowstart[i] = sh[t] - v;  // exclusive within block
    if (t == 1023) g_blocksums[blockIdx.x] = sh[1023];
}

// apply block offsets + compute norms (fused)
__global__ void k_scan23() {
    __shared__ int bs[SCAN_NB];
    __shared__ int pre[SCAN_NB];
    int t = threadIdx.x;
    if (t < SCAN_NB) bs[t] = g_blocksums[t];
    __syncthreads();
    if (t == 0) {
        int run = 0;
        #pragma unroll 1
        for (int i = 0; i < SCAN_NB; ++i) { pre[i] = run; run += bs[i]; }
    }
    __syncthreads();
    int i = blockIdx.x * blockDim.x + t;
    if (i < NN) {
        g_rowstart[i] += pre[i >> 10];
        g_ns[i] = rsqrtf(fmaxf((float)g_outdeg[i], 1.0f));
        g_nd[i] = rsqrtf(fmaxf((float)g_indeg[i], 1.0f));
    }
    if (i == 0) g_rowstart[NN] = NE;
}

// atomic-free CSR fill: pos = rowstart[dst] + rank
__global__ void k_csr(const int4* __restrict__ src4, const int4* __restrict__ dst4) {
    int e = blockIdx.x * blockDim.x + threadIdx.x;
    if (e < NE / 4) {
        int4 s = src4[e];
        int4 d = dst4[e];
        int4 r = ((const int4*)g_rank)[e];
        g_csr[g_rowstart[d.x] + r.x] = s.x;
        g_csr[g_rowstart[d.y] + r.y] = s.y;
        g_csr[g_rowstart[d.z] + r.z] = s.z;
        g_csr[g_rowstart[d.w] + r.w] = s.w;
    }
}

// ---------------- SpMM: warp per node, fp16 gather, dual fp32 accum -----------
__device__ __forceinline__ void acc_edge(uint2 u, float n, float* a1, float* a2) {
    float2 f0 = __half22float2(*reinterpret_cast<__half2*>(&u.x));
    float2 f1 = __half22float2(*reinterpret_cast<__half2*>(&u.y));
    a2[0] += f0.x; a2[1] += f0.y; a2[2] += f1.x; a2[3] += f1.y;
    a1[0] = fmaf(f0.x, n, a1[0]); a1[1] = fmaf(f0.y, n, a1[1]);
    a1[2] = fmaf(f1.x, n, a1[2]); a1[3] = fmaf(f1.y, n, a1[3]);
}

__global__ __launch_bounds__(256) void k_spmm(const uint2* __restrict__ x) {
    int w    = (blockIdx.x * 256 + threadIdx.x) >> 5;
    int lane = threadIdx.x & 31;
    if (w >= NN) return;
    int s = g_rowstart[w];
    int e = g_rowstart[w + 1];
    float a1[4] = {0.f, 0.f, 0.f, 0.f};
    float a2[4] = {0.f, 0.f, 0.f, 0.f};
    int p = s;
    for (; p + 3 < e; p += 4) {
        int j0 = g_csr[p],     j1 = g_csr[p + 1];
        int j2 = g_csr[p + 2], j3 = g_csr[p + 3];
        float n0 = g_ns[j0], n1 = g_ns[j1], n2 = g_ns[j2], n3 = g_ns[j3];
        uint2 u0 = x[(size_t)j0 * 32 + lane];
        uint2 u1 = x[(size_t)j1 * 32 + lane];
        uint2 u2 = x[(size_t)j2 * 32 + lane];
        uint2 u3 = x[(size_t)j3 * 32 + lane];
        acc_edge(u0, n0, a1, a2);
        acc_edge(u1, n1, a1, a2);
        acc_edge(u2, n2, a1, a2);
        acc_edge(u3, n3, a1, a2);
    }
    for (; p < e; ++p) {
        int j0 = g_csr[p];
        float n0 = g_ns[j0];
        uint2 u0 = x[(size_t)j0 * 32 + lane];
        acc_edge(u0, n0, a1, a2);
    }
    float nd = g_nd[w];
    uint4 o1, o2;
    o1.x = f2tf(a1[0] * nd); o1.y = f2tf(a1[1] * nd);
    o1.z = f2tf(a1[2] * nd); o1.w = f2tf(a1[3] * nd);
    o2.x = f2tf(a2[0]); o2.y = f2tf(a2[1]); o2.z = f2tf(a2[2]); o2.w = f2tf(a2[3]);
    g_y[(size_t)w * 64 + lane]      = o1;
    g_y[(size_t)w * 64 + 32 + lane] = o2;
}

// ---------------- GEMM: C[M,BN] = A[M,256] @ B[256,BN] + bias ----------------
// A, B are pre-converted tf32 bit patterns. cp.async double-buffered pipeline.
// HALFOUT: emit __half (hidden layers); else fp32 (final output).
template <int BN, bool RELU, bool HALFOUT>
__global__ __launch_bounds__(256) void k_gemm(
    const uint32_t* __restrict__ A, const uint32_t* __restrict__ Bw,
    const float* __restrict__ bias, void* __restrict__ Cv, int M)
{
    constexpr int BM = 128, BK = 32, K = 256;
    constexpr int AS = 36;         // padded A stride
    constexpr int BS = BN + 8;     // padded B stride
    constexpr int NT = BN / 16;    // n-tiles per warp
    constexpr int ABUF = BM * AS;
    constexpr int BBUF = BK * BS;

    extern __shared__ uint32_t dynsmem[];
    uint32_t* sA = dynsmem;
    uint32_t* sB = dynsmem + 2 * ABUF;
    const uint32_t saddrA = (uint32_t)__cvta_generic_to_shared(sA);
    const uint32_t saddrB = (uint32_t)__cvta_generic_to_shared(sB);

    const int tid  = threadIdx.x;
    const int warp = tid >> 5, lane = tid & 31;
    const int grp  = lane >> 2, tig = lane & 3;
    const int wm   = (warp >> 1) * 32;
    const int wn   = (warp & 1) * (BN / 2);
    const int blockRow = blockIdx.x * BM;

    auto stage = [&](int kc, int buf) {
        #pragma unroll
        for (int it = 0; it < 4; ++it) {      // A tile: 128x32
            int idx = tid + it * 256;
            int r = idx >> 3, c = (idx & 7) * 4;
            cp16(saddrA + (uint32_t)(buf * ABUF + r * AS + c) * 4,
                 A + (size_t)(blockRow + r) * K + kc * BK + c);
        }
        #pragma unroll
        for (int it = 0; it < (BK * BN / 4) / 256; ++it) {  // B tile: 32xBN
            int idx = tid + it * 256;
            int r = idx / (BN / 4), c = (idx % (BN / 4)) * 4;
            cp16(saddrB + (uint32_t)(buf * BBUF + r * BS + c) * 4,
                 Bw + (size_t)(kc * BK + r) * BN + c);
        }
        cpcommit();
    };

    float acc[2][NT][4];
    #pragma unroll
    for (int mt = 0; mt < 2; mt++)
        #pragma unroll
        for (int nt = 0; nt < NT; nt++)
            #pragma unroll
            for (int r = 0; r < 4; r++) acc[mt][nt][r] = 0.f;

    stage(0, 0);
    #pragma unroll
    for (int kc = 0; kc < K / BK; ++kc) {
        int buf = kc & 1;
        if (kc + 1 < K / BK) {
            stage(kc + 1, buf ^ 1);
            cpwait<1>();
        } else {
            cpwait<0>();
        }
        __syncthreads();

        const uint32_t* cA = sA + buf * ABUF;
        const uint32_t* cB = sB + buf * BBUF;
        #pragma unroll
        for (int ks = 0; ks < 4; ++ks) {
            uint32_t af[2][4];
            #pragma unroll
            for (int mt = 0; mt < 2; mt++) {
                int row = wm + mt * 16 + grp;
                af[mt][0] = cA[row * AS + ks * 8 + tig];
                af[mt][1] = cA[(row + 8) * AS + ks * 8 + tig];
                af[mt][2] = cA[row * AS + ks * 8 + tig + 4];
                af[mt][3] = cA[(row + 8) * AS + ks * 8 + tig + 4];
            }
            uint32_t bf[NT][2];
            #pragma unroll
            for (int nt = 0; nt < NT; nt++) {
                int col = wn + nt * 8 + grp;
                bf[nt][0] = cB[(ks * 8 + tig) * BS + col];
                bf[nt][1] = cB[(ks * 8 + tig + 4) * BS + col];
            }
            #pragma unroll
            for (int mt = 0; mt < 2; mt++)
                #pragma unroll
                for (int nt = 0; nt < NT; nt++)
                    mma_tf32(acc[mt][nt], af[mt], bf[nt]);
        }
        __syncthreads();
    }

    // epilogue: bias (+relu), half2 or float2 stores
    #pragma unroll
    for (int mt = 0; mt < 2; ++mt) {
        int r0 = blockRow + wm + mt * 16 + grp;
        int r1 = r0 + 8;
        #pragma unroll
        for (int nt = 0; nt < NT; ++nt) {
            int col = wn + nt * 8 + 2 * tig;
            float b0v = bias[col], b1v = bias[col + 1];
            float v0 = acc[mt][nt][0] + b0v;
            float v1 = acc[mt][nt][1] + b1v;
            float v2 = acc[mt][nt][2] + b0v;
            float v3 = acc[mt][nt][3] + b1v;
            if (RELU) {
                v0 = fmaxf(v0, 0.f); v1 = fmaxf(v1, 0.f);
                v2 = fmaxf(v2, 0.f); v3 = fmaxf(v3, 0.f);
            }
            if (HALFOUT) {
                __half* C = (__half*)Cv;
                if (r0 < M)
                    *reinterpret_cast<__half2*>(&C[(size_t)r0 * BN + col]) =
                        __floats2half2_rn(v0, v1);
                if (r1 < M)
                    *reinterpret_cast<__half2*>(&C[(size_t)r1 * BN + col]) =
                        __floats2half2_rn(v2, v3);
            } else {
                float* C = (float*)Cv;
                if (r0 < M)
                    *reinterpret_cast<float2*>(&C[(size_t)r0 * BN + col]) = make_float2(v0, v1);
                if (r1 < M)
                    *reinterpret_cast<float2*>(&C[(size_t)r1 * BN + col]) = make_float2(v2, v3);
            }
        }
    }
}

// ---------------- launcher ----------------------------------------------------
extern "C" void kernel_launch(void* const* d_in, const int* in_sizes, int n_in,
                              void* d_out, int out_size) {
    const float* raw_x = (const float*)d_in[0];
    const int*   src   = (const int*)d_in[1];
    const int*   dst   = (const int*)d_in[2];
    const float* w0    = (const float*)d_in[3];
    const float* b0    = (const float*)d_in[4];
    const float* w1    = (const float*)d_in[5];
    const float* b1    = (const float*)d_in[6];
    const float* w2    = (const float*)d_in[7];
    const float* b2    = (const float*)d_in[8];
    const float* rw0   = (const float*)d_in[9];
    const float* rw1   = (const float*)d_in[10];
    const float* rw2   = (const float*)d_in[11];
    float* out = (float*)d_out;

    void *py = nullptr, *pxh = nullptr;
    void *pw0 = nullptr, *pw1 = nullptr, *pw2 = nullptr;
    cudaGetSymbolAddress(&py, g_y);
    cudaGetSymbolAddress(&pxh, g_xh);
    cudaGetSymbolAddress(&pw0, g_wt0);
    cudaGetSymbolAddress(&pw1, g_wt1);
    cudaGetSymbolAddress(&pw2, g_wt2);

    constexpr int SMEM128 = (2 * 128 * 36 + 2 * 32 * 136) * 4;  // 71680
    constexpr int SMEM64  = (2 * 128 * 36 + 2 * 32 * 72) * 4;   // 55296
    cudaFuncSetAttribute(k_gemm<128, true, true>,
                         cudaFuncAttributeMaxDynamicSharedMemorySize, SMEM128);
    cudaFuncSetAttribute(k_gemm<64, false, false>,
                         cudaFuncAttributeMaxDynamicSharedMemorySize, SMEM64);

    const int TB = 256;
    // fused prep (weights->tf32, zero degs, raw_x->fp16), then graph build
    k_prep<<<(3331920 + TB - 1) / TB, TB>>>((const float4*)raw_x,
                                            w0, rw0, w1, rw1, w2, rw2);
    k_deg<<<(NE / 4 + TB - 1) / TB, TB>>>((const int4*)src, (const int4*)dst);
    k_scan1<<<SCAN_NB, 1024>>>();
    k_scan23<<<(NN + TB - 1) / TB, TB>>>();
    k_csr<<<(NE / 4 + TB - 1) / TB, TB>>>((const int4*)src, (const int4*)dst);

    const int SPMM_BLOCKS = (NN * 32 + TB - 1) / TB;  // one warp per node
    const int GEMM_BLOCKS = NN_PAD / 128;             // 782

    // layer 1
    k_spmm<<<SPMM_BLOCKS, TB>>>((const uint2*)pxh);
    k_gemm<128, true, true><<<GEMM_BLOCKS, TB, SMEM128>>>(
        (const uint32_t*)py, (const uint32_t*)pw0, b0, pxh, NN);
    // layer 2
    k_spmm<<<SPMM_BLOCKS, TB>>>((const uint2*)pxh);
    k_gemm<128, true, true><<<GEMM_BLOCKS, TB, SMEM128>>>(
        (const uint32_t*)py, (const uint32_t*)pw1, b1, pxh, NN);
    // layer 3 (no relu, F=64) -> d_out
    k_spmm<<<SPMM_BLOCKS, TB>>>((const uint2*)pxh);
    k_gemm<64, false, false><<<GEMM_BLOCKS, TB, SMEM64>>>(
        (const uint32_t*)py, (const uint32_t*)pw2, b2, out, NN);
}